// round 9
// baseline (speedup 1.0000x reference)
#include <cuda_runtime.h>
#include <cuda_fp16.h>

#define N_NODES 50000
#define N_EDGES 800000
#define HID 64
#define SCAN_BLOCKS ((N_NODES + 255) / 256)       // 196
#define EPAIR_BLOCKS ((N_EDGES / 2 + 255) / 256)  // 1563

// ---- scratch (static device globals; zero-initialized at load) ----
__device__ int    g_deg[N_NODES];       // re-zeroed by k_scan each call
__device__ int    g_off[N_NODES + 1];
__device__ int    g_rank[N_EDGES];      // packed: (rank << 16) | dst
__device__ int    g_state[SCAN_BLOCKS]; // lookback flags; zeroed in k_count
__device__ int    g_aggval[SCAN_BLOCKS];
__device__ int    g_preval[SCAN_BLOCKS];
__device__ int    g_srcidx[N_EDGES];
__device__ float  g_A[N_NODES * HID];
__device__ __half g_Bh[N_NODES * HID];  // B table in fp16
__device__ __half g_Hh[N_NODES * HID];  // H in fp16 (layer-1 output)

typedef unsigned long long ull;

// ---- packed f32x2 helpers (identical .rn rounding to scalar fp32) ----
__device__ __forceinline__ ull pack2(float x, float y) {
    ull r;
    asm("mov.b64 %0, {%1, %2};" : "=l"(r) : "f"(x), "f"(y));
    return r;
}
__device__ __forceinline__ void unpack2(ull v, float& x, float& y) {
    asm("mov.b64 {%0, %1}, %2;" : "=f"(x), "=f"(y) : "l"(v));
}
__device__ __forceinline__ void fma2(ull& acc, ull a, ull b) {
    asm("fma.rn.f32x2 %0, %1, %2, %0;" : "+l"(acc) : "l"(a), "l"(b));
}

// ---------------- CSR build ----------------
// vectorized single atomic pass: degree histogram + packed (rank|dst) per edge
// block 0 also resets the lookback state flags for k_scan
__global__ void k_count(const int* __restrict__ ei) {
    if (blockIdx.x == 0 && threadIdx.x < SCAN_BLOCKS) g_state[threadIdx.x] = 0;
    int t = blockIdx.x * blockDim.x + threadIdx.x;
    int e = 2 * t;
    if (e + 1 < N_EDGES) {
        int2 d = *(const int2*)&ei[N_EDGES + e];
        int r0 = atomicAdd(&g_deg[d.x], 1);
        int r1 = atomicAdd(&g_deg[d.y], 1);
        *(int2*)&g_rank[e] = make_int2((r0 << 16) | d.x, (r1 << 16) | d.y);
    } else if (e < N_EDGES) {
        int dst = ei[N_EDGES + e];
        int r = atomicAdd(&g_deg[dst], 1);
        g_rank[e] = (r << 16) | dst;
    }
}

// single-pass exclusive scan with decoupled lookback; re-zeroes g_deg
__global__ void k_scan() {
    __shared__ int sh[256];
    __shared__ int s_prefix;
    int tid = threadIdx.x, b = blockIdx.x;
    int i = b * 256 + tid;
    int v = (i < N_NODES) ? g_deg[i] : 0;
    sh[tid] = v;
    __syncthreads();
#pragma unroll
    for (int ofs = 1; ofs < 256; ofs <<= 1) {
        int t = (tid >= ofs) ? sh[tid - ofs] : 0;
        __syncthreads();
        sh[tid] += t;
        __syncthreads();
    }
    int total = sh[255];
    if (tid == 0) {
        g_aggval[b] = total;
        __threadfence();
        atomicExch(&g_state[b], 1);
        int run = 0;
        int j = b - 1;
        while (j >= 0) {
            int s;
            do { s = atomicAdd(&g_state[j], 0); } while (s == 0);
            __threadfence();
            if (s == 2) { run += g_preval[j]; break; }
            run += g_aggval[j];
            j--;
        }
        g_preval[b] = run + total;   // inclusive prefix through block b
        __threadfence();
        atomicExch(&g_state[b], 2);
        s_prefix = run;              // exclusive prefix for this block
    }
    __syncthreads();
    int prefix = s_prefix;
    if (i < N_NODES) {
        g_off[i] = prefix + sh[tid] - v;
        g_deg[i] = 0;                // invariant for next invocation
    }
    if (b == SCAN_BLOCKS - 1 && tid == 255) g_off[N_NODES] = prefix + total;
}

// atomic-free fill from packed rank|dst: position = off[dst] + rank
__global__ void k_fill(const int* __restrict__ ei) {
    int t = blockIdx.x * blockDim.x + threadIdx.x;
    int e = 2 * t;
    if (e + 1 < N_EDGES) {
        int2 r = *(const int2*)&g_rank[e];
        int2 s = *(const int2*)&ei[e];
        g_srcidx[g_off[r.x & 0xFFFF] + (r.x >> 16)] = s.x;
        g_srcidx[g_off[r.y & 0xFFFF] + (r.y >> 16)] = s.y;
    } else if (e < N_EDGES) {
        int r = g_rank[e];
        g_srcidx[g_off[r & 0xFFFF] + (r >> 16)] = ei[e];
    }
}

// ---------------- layer-1 node pre-GEMMs: A = x@(Wtop-Wbot)+b, B = x@Wbot ----
__global__ void __launch_bounds__(256) k_nodeAB1(const float* __restrict__ x,
                                                 const float* __restrict__ w1a,
                                                 const float* __restrict__ b1a) {
    __shared__ float wd[16 * 64];
    __shared__ float wb[16 * 64];
    __shared__ float bshm[64];
    int tid = threadIdx.x;
    for (int i = tid; i < 16 * 64; i += 256) {
        float top = w1a[i];
        float bot = w1a[16 * 64 + i];
        wd[i] = top - bot;
        wb[i] = bot;
    }
    if (tid < 64) bshm[tid] = b1a[tid];
    __syncthreads();
    int warp = tid >> 5, lane = tid & 31;
    int nbase = (blockIdx.x * 8 + warp) * 4;
#pragma unroll
    for (int ni = 0; ni < 4; ni++) {
        int node = nbase + ni;
        if (node >= N_NODES) break;
        float xown = (lane < 16) ? x[node * 16 + lane] : 0.f;
        ull A = pack2(bshm[2 * lane], bshm[2 * lane + 1]);
        ull C = 0ULL;
#pragma unroll
        for (int k = 0; k < 16; k++) {
            float xk = __shfl_sync(0xffffffffu, xown, k);
            ull x2 = pack2(xk, xk);
            fma2(A, x2, *(const ull*)&wd[k * 64 + lane * 2]);
            fma2(C, x2, *(const ull*)&wb[k * 64 + lane * 2]);
        }
        float ax, ay, cx, cy;
        unpack2(A, ax, ay);
        unpack2(C, cx, cy);
        *(float2*)&g_A[node * 64 + lane * 2] = make_float2(ax, ay);
        ((__half2*)g_Bh)[node * 32 + lane] = __floats2half2_rn(cx, cy);
    }
}

// ---------------- edge gather + post-GEMM (both layers; FINAL fuses projection)
// per node i: acc = mean_e relu(A[i] + B[src_e]); h = relu(acc@Wp + bp)
// Index loads are coalesced once per batch and distributed via shfl.
template <int FINAL>
__global__ void __launch_bounds__(256) k_gather_t(const float* __restrict__ Wp,
                                                  const float* __restrict__ bp,
                                                  const float* __restrict__ wl,
                                                  const float* __restrict__ bl,
                                                  float* __restrict__ out) {
    __shared__ float wsh[64 * 64];
    __shared__ float bshm[64];
    __shared__ float accsh[8][64][4];   // [warp][channel][node-in-warp]
    int tid = threadIdx.x;
    for (int i = tid; i < 64 * 64; i += 256) wsh[i] = Wp[i];
    if (tid < 64) bshm[tid] = bp[tid];
    __syncthreads();
    int warp = tid >> 5, lane = tid & 31;
    int nbase = (blockIdx.x * 8 + warp) * 4;
    const __half2* __restrict__ Bh2 = (const __half2*)g_Bh;

    int dg[4];
#pragma unroll
    for (int ni = 0; ni < 4; ni++) {
        int node = nbase + ni;
        float acc0 = 0.f, acc1 = 0.f;
        int deg = 0;
        if (node < N_NODES) {
            int e0 = g_off[node], e1 = g_off[node + 1];
            deg = e1 - e0;
            float2 a = *(const float2*)&g_A[node * 64 + lane * 2];
            int e = e0;
            for (; e + 8 <= e1; e += 8) {
                int myidx = g_srcidx[e + (lane & 7)];   // 1 coalesced LDG
                int s[8];
#pragma unroll
                for (int j = 0; j < 8; j++) s[j] = __shfl_sync(0xffffffffu, myidx, j);
                float2 b[8];
#pragma unroll
                for (int j = 0; j < 8; j++) b[j] = __half22float2(Bh2[s[j] * 32 + lane]);
#pragma unroll
                for (int j = 0; j < 8; j++) {
                    acc0 += fmaxf(a.x + b[j].x, 0.f);
                    acc1 += fmaxf(a.y + b[j].y, 0.f);
                }
            }
            if (e + 4 <= e1) {
                int myidx = g_srcidx[e + (lane & 3)];
                int s[4];
#pragma unroll
                for (int j = 0; j < 4; j++) s[j] = __shfl_sync(0xffffffffu, myidx, j);
                float2 b[4];
#pragma unroll
                for (int j = 0; j < 4; j++) b[j] = __half22float2(Bh2[s[j] * 32 + lane]);
#pragma unroll
                for (int j = 0; j < 4; j++) {
                    acc0 += fmaxf(a.x + b[j].x, 0.f);
                    acc1 += fmaxf(a.y + b[j].y, 0.f);
                }
                e += 4;
            }
            for (; e < e1; e++) {
                int s = g_srcidx[e];
                float2 bb = __half22float2(Bh2[s * 32 + lane]);
                acc0 += fmaxf(a.x + bb.x, 0.f);
                acc1 += fmaxf(a.y + bb.y, 0.f);
            }
            if (deg > 0) {
                float inv = 1.0f / (float)deg;
                acc0 *= inv;
                acc1 *= inv;
            }
        }
        dg[ni] = deg;
        accsh[warp][2 * lane][ni] = acc0;
        accsh[warp][2 * lane + 1][ni] = acc1;
    }
    __syncwarp();

    // fused 4-node epilogue GEMM in packed f32x2
    ull accA[4];
    {
        ull binit = pack2(bshm[2 * lane], bshm[2 * lane + 1]);
#pragma unroll
        for (int ni = 0; ni < 4; ni++) accA[ni] = binit;
    }
#pragma unroll 8
    for (int k = 0; k < 64; k++) {
        float4 av = *(const float4*)&accsh[warp][k][0];
        ull w2 = *(const ull*)&wsh[k * 64 + 2 * lane];
        fma2(accA[0], pack2(av.x, av.x), w2);
        fma2(accA[1], pack2(av.y, av.y), w2);
        fma2(accA[2], pack2(av.z, av.z), w2);
        fma2(accA[3], pack2(av.w, av.w), w2);
    }

    if (FINAL == 0) {
#pragma unroll
        for (int ni = 0; ni < 4; ni++) {
            int node = nbase + ni;
            if (node >= N_NODES) break;
            float o0, o1;
            unpack2(accA[ni], o0, o1);
            if (dg[ni] > 0) { o0 = fmaxf(o0, 0.f); o1 = fmaxf(o1, 0.f); }
            else            { o0 = 0.f; o1 = 0.f; }
            ((__half2*)g_Hh)[node * 32 + lane] = __floats2half2_rn(o0, o1);
        }
    } else {
        float4 w = *(const float4*)&wl[lane * 4];
        float bl0 = bl[0], bl1 = bl[1];
#pragma unroll
        for (int ni = 0; ni < 4; ni++) {
            int node = nbase + ni;
            if (node >= N_NODES) break;
            float o0, o1;
            unpack2(accA[ni], o0, o1);
            if (dg[ni] > 0) { o0 = fmaxf(o0, 0.f); o1 = fmaxf(o1, 0.f); }
            else            { o0 = 0.f; o1 = 0.f; }
            float p0 = o0 * w.x + o1 * w.z;
            float p1 = o0 * w.y + o1 * w.w;
#pragma unroll
            for (int ofs = 16; ofs > 0; ofs >>= 1) {
                p0 += __shfl_xor_sync(0xffffffffu, p0, ofs);
                p1 += __shfl_xor_sync(0xffffffffu, p1, ofs);
            }
            if (lane == 0) {
                out[node * 2 + 0] = p0 + bl0;
                out[node * 2 + 1] = p1 + bl1;
            }
        }
    }
}

// ---------------- layer-2 node pre-GEMMs from H(fp16): 8 nodes/warp, f32x2 ---
__global__ void __launch_bounds__(256) k_nodeAB2(const float* __restrict__ w2a,
                                                 const float* __restrict__ b2a) {
    __shared__ float wdb[64 * 32 * 4];
    __shared__ float bshm[64];
    __shared__ float hsh[8][64 * 8];
    int tid = threadIdx.x;
    for (int idx = tid; idx < 64 * 64; idx += 256) {
        int k = idx >> 6, col = idx & 63;
        float top = w2a[idx];
        float bot = w2a[64 * 64 + idx];
        int ln = col >> 1, comp = col & 1;
        wdb[(k * 32 + ln) * 4 + comp]     = top - bot;
        wdb[(k * 32 + ln) * 4 + 2 + comp] = bot;
    }
    if (tid < 64) bshm[tid] = b2a[tid];
    __syncthreads();
    int warp = tid >> 5, lane = tid & 31;
    int nbase = (blockIdx.x * 8 + warp) * 8;
    const __half2* __restrict__ Hh2 = (const __half2*)g_Hh;

#pragma unroll
    for (int ni = 0; ni < 8; ni++) {
        int node = nbase + ni;
        float2 h = (node < N_NODES) ? __half22float2(Hh2[node * 32 + lane])
                                    : make_float2(0.f, 0.f);
        hsh[warp][(2 * lane) * 8 + ni]     = h.x;
        hsh[warp][(2 * lane + 1) * 8 + ni] = h.y;
    }
    __syncwarp();

    ull A[8], C[8];
    ull binit = pack2(bshm[2 * lane], bshm[2 * lane + 1]);
#pragma unroll
    for (int ni = 0; ni < 8; ni++) { A[ni] = binit; C[ni] = 0ULL; }

#pragma unroll 4
    for (int k = 0; k < 64; k++) {
        float4 h03 = *(const float4*)&hsh[warp][k * 8];
        float4 h47 = *(const float4*)&hsh[warp][k * 8 + 4];
        const ull* wp = (const ull*)&wdb[(k * 32 + lane) * 4];
        ull wd2 = wp[0], wb2 = wp[1];
        ull hh;
        hh = pack2(h03.x, h03.x); fma2(A[0], hh, wd2); fma2(C[0], hh, wb2);
        hh = pack2(h03.y, h03.y); fma2(A[1], hh, wd2); fma2(C[1], hh, wb2);
        hh = pack2(h03.z, h03.z); fma2(A[2], hh, wd2); fma2(C[2], hh, wb2);
        hh = pack2(h03.w, h03.w); fma2(A[3], hh, wd2); fma2(C[3], hh, wb2);
        hh = pack2(h47.x, h47.x); fma2(A[4], hh, wd2); fma2(C[4], hh, wb2);
        hh = pack2(h47.y, h47.y); fma2(A[5], hh, wd2); fma2(C[5], hh, wb2);
        hh = pack2(h47.z, h47.z); fma2(A[6], hh, wd2); fma2(C[6], hh, wb2);
        hh = pack2(h47.w, h47.w); fma2(A[7], hh, wd2); fma2(C[7], hh, wb2);
    }
#pragma unroll
    for (int ni = 0; ni < 8; ni++) {
        int node = nbase + ni;
        if (node >= N_NODES) break;
        float ax, ay, cx, cy;
        unpack2(A[ni], ax, ay);
        unpack2(C[ni], cx, cy);
        *(float2*)&g_A[node * 64 + lane * 2] = make_float2(ax, ay);
        ((__half2*)g_Bh)[node * 32 + lane] = __floats2half2_rn(cx, cy);
    }
}

extern "C" void kernel_launch(void* const* d_in, const int* in_sizes, int n_in,
                              void* d_out, int out_size) {
    const float* x   = (const float*)d_in[0];
    const int*   ei  = (const int*)d_in[1];   // int32 (JAX default x64 disabled)
    const float* w1a = (const float*)d_in[2];
    const float* b1a = (const float*)d_in[3];
    const float* w1b = (const float*)d_in[4];
    const float* b1b = (const float*)d_in[5];
    const float* w2a = (const float*)d_in[6];
    const float* b2a = (const float*)d_in[7];
    const float* w2b = (const float*)d_in[8];
    const float* b2b = (const float*)d_in[9];
    const float* wl  = (const float*)d_in[10];
    const float* bl  = (const float*)d_in[11];
    float* out = (float*)d_out;

    // CSR build: count(+rank,+state reset) -> lookback scan -> fill
    k_count<<<EPAIR_BLOCKS, 256>>>(ei);
    k_scan<<<SCAN_BLOCKS, 256>>>();
    k_fill<<<EPAIR_BLOCKS, 256>>>(ei);

    int gather_blocks = (N_NODES + 31) / 32;   // 8 warps x 4 nodes
    int ab2_blocks    = (N_NODES + 63) / 64;   // 8 warps x 8 nodes

    // layer 1 (AB1 is launch #4 -> gets profiled)
    k_nodeAB1<<<gather_blocks, 256>>>(x, w1a, b1a);
    k_gather_t<0><<<gather_blocks, 256>>>(w1b, b1b, wl, bl, out);

    // layer 2 (+ fused final projection)
    k_nodeAB2<<<ab2_blocks, 256>>>(w2a, b2a);
    k_gather_t<1><<<gather_blocks, 256>>>(w2b, b2b, wl, bl, out);
}

// round 10
// speedup vs baseline: 1.0417x; 1.0417x over previous
#include <cuda_runtime.h>
#include <cuda_fp16.h>

#define N_NODES 50000
#define N_EDGES 800000
#define HID 64
#define SCAN_BLOCKS ((N_NODES + 255) / 256)       // 196
#define EPAIR_BLOCKS ((N_EDGES / 2 + 255) / 256)  // 1563

// ---- scratch (static device globals; zero-initialized at load) ----
__device__ int    g_deg[N_NODES];       // re-zeroed by k_scan23 each call
__device__ int    g_off[N_NODES + 1];
__device__ int    g_rank[N_EDGES];      // packed: (rank << 16) | dst
__device__ int    g_bsum[256];
__device__ int    g_srcidx[N_EDGES];
__device__ float  g_A[N_NODES * HID];
__device__ __half g_Bh[N_NODES * HID];  // B table in fp16
__device__ __half g_Hh[N_NODES * HID];  // H in fp16 (layer-1 output)

typedef unsigned long long ull;

// ---- packed f32x2 helpers (identical .rn rounding to scalar fp32) ----
__device__ __forceinline__ ull pack2(float x, float y) {
    ull r;
    asm("mov.b64 %0, {%1, %2};" : "=l"(r) : "f"(x), "f"(y));
    return r;
}
__device__ __forceinline__ void unpack2(ull v, float& x, float& y) {
    asm("mov.b64 {%0, %1}, %2;" : "=f"(x), "=f"(y) : "l"(v));
}
__device__ __forceinline__ void fma2(ull& acc, ull a, ull b) {
    asm("fma.rn.f32x2 %0, %1, %2, %0;" : "+l"(acc) : "l"(a), "l"(b));
}

// ---------------- CSR build ----------------
// vectorized single atomic pass: degree histogram + packed (rank|dst) per edge
__global__ void k_count(const int* __restrict__ ei) {
    int t = blockIdx.x * blockDim.x + threadIdx.x;
    int e = 2 * t;
    if (e + 1 < N_EDGES) {
        int2 d = *(const int2*)&ei[N_EDGES + e];
        int r0 = atomicAdd(&g_deg[d.x], 1);
        int r1 = atomicAdd(&g_deg[d.y], 1);
        *(int2*)&g_rank[e] = make_int2((r0 << 16) | d.x, (r1 << 16) | d.y);
    } else if (e < N_EDGES) {
        int dst = ei[N_EDGES + e];
        int r = atomicAdd(&g_deg[dst], 1);
        g_rank[e] = (r << 16) | dst;
    }
}

__global__ void k_scan1() {
    __shared__ int sh[256];
    int tid = threadIdx.x;
    int i = blockIdx.x * 256 + tid;
    int v = (i < N_NODES) ? g_deg[i] : 0;
    sh[tid] = v;
    __syncthreads();
#pragma unroll
    for (int ofs = 1; ofs < 256; ofs <<= 1) {
        int t = (tid >= ofs) ? sh[tid - ofs] : 0;
        __syncthreads();
        sh[tid] += t;
        __syncthreads();
    }
    if (i < N_NODES) g_off[i] = sh[tid] - v;
    if (tid == 255) g_bsum[blockIdx.x] = sh[255];
}

// merged scan2+scan3 + re-zero g_deg for next invocation
__global__ void k_scan23() {
    __shared__ int sh[256];
    int tid = threadIdx.x;
    int v = (tid < SCAN_BLOCKS) ? g_bsum[tid] : 0;
    sh[tid] = v;
    __syncthreads();
#pragma unroll
    for (int ofs = 1; ofs < 256; ofs <<= 1) {
        int t = (tid >= ofs) ? sh[tid - ofs] : 0;
        __syncthreads();
        sh[tid] += t;
        __syncthreads();
    }
    int prefix = (blockIdx.x == 0) ? 0 : sh[blockIdx.x - 1];
    int i = blockIdx.x * 256 + tid;
    if (i < N_NODES) {
        g_off[i] += prefix;
        g_deg[i] = 0;
    }
    if (blockIdx.x == 0 && tid == 0) g_off[N_NODES] = sh[255];
}

// atomic-free fill from packed rank|dst: position = off[dst] + rank
__global__ void k_fill(const int* __restrict__ ei) {
    int t = blockIdx.x * blockDim.x + threadIdx.x;
    int e = 2 * t;
    if (e + 1 < N_EDGES) {
        int2 r = *(const int2*)&g_rank[e];
        int2 s = *(const int2*)&ei[e];
        g_srcidx[g_off[r.x & 0xFFFF] + (r.x >> 16)] = s.x;
        g_srcidx[g_off[r.y & 0xFFFF] + (r.y >> 16)] = s.y;
    } else if (e < N_EDGES) {
        int r = g_rank[e];
        g_srcidx[g_off[r & 0xFFFF] + (r >> 16)] = ei[e];
    }
}

// ---------------- layer-1 node pre-GEMMs: A = x@(Wtop-Wbot)+b, B = x@Wbot ----
__global__ void __launch_bounds__(256, 4) k_nodeAB1(const float* __restrict__ x,
                                                    const float* __restrict__ w1a,
                                                    const float* __restrict__ b1a) {
    __shared__ float wd[16 * 64];
    __shared__ float wb[16 * 64];
    __shared__ float bshm[64];
    int tid = threadIdx.x;
    for (int i = tid; i < 16 * 64; i += 256) {
        float top = w1a[i];
        float bot = w1a[16 * 64 + i];
        wd[i] = top - bot;
        wb[i] = bot;
    }
    if (tid < 64) bshm[tid] = b1a[tid];
    __syncthreads();
    int warp = tid >> 5, lane = tid & 31;
    int nbase = (blockIdx.x * 8 + warp) * 4;
#pragma unroll
    for (int ni = 0; ni < 4; ni++) {
        int node = nbase + ni;
        if (node >= N_NODES) break;
        float xown = (lane < 16) ? x[node * 16 + lane] : 0.f;
        ull A = pack2(bshm[2 * lane], bshm[2 * lane + 1]);
        ull C = 0ULL;
#pragma unroll
        for (int k = 0; k < 16; k++) {
            float xk = __shfl_sync(0xffffffffu, xown, k);
            ull x2 = pack2(xk, xk);
            fma2(A, x2, *(const ull*)&wd[k * 64 + lane * 2]);
            fma2(C, x2, *(const ull*)&wb[k * 64 + lane * 2]);
        }
        float ax, ay, cx, cy;
        unpack2(A, ax, ay);
        unpack2(C, cx, cy);
        *(float2*)&g_A[node * 64 + lane * 2] = make_float2(ax, ay);
        ((__half2*)g_Bh)[node * 32 + lane] = __floats2half2_rn(cx, cy);
    }
}

// ---------------- edge gather + post-GEMM (both layers; FINAL fuses projection)
// per node i: acc = mean_e relu(A[i] + B[src_e]); h = relu(acc@Wp + bp)
// (R5/R8-proven structure; reg-capped for 4 blocks/SM)
template <int FINAL>
__global__ void __launch_bounds__(256, 4) k_gather_t(const float* __restrict__ Wp,
                                                     const float* __restrict__ bp,
                                                     const float* __restrict__ wl,
                                                     const float* __restrict__ bl,
                                                     float* __restrict__ out) {
    __shared__ float wsh[64 * 64];
    __shared__ float bshm[64];
    __shared__ float accsh[8][64][4];   // [warp][channel][node-in-warp]
    int tid = threadIdx.x;
    for (int i = tid; i < 64 * 64; i += 256) wsh[i] = Wp[i];
    if (tid < 64) bshm[tid] = bp[tid];
    __syncthreads();
    int warp = tid >> 5, lane = tid & 31;
    int nbase = (blockIdx.x * 8 + warp) * 4;
    const __half2* __restrict__ Bh2 = (const __half2*)g_Bh;

    int dg[4];
#pragma unroll
    for (int ni = 0; ni < 4; ni++) {
        int node = nbase + ni;
        float acc0 = 0.f, acc1 = 0.f;
        int deg = 0;
        if (node < N_NODES) {
            int e0 = g_off[node], e1 = g_off[node + 1];
            deg = e1 - e0;
            float2 a = *(const float2*)&g_A[node * 64 + lane * 2];
            int e = e0;
            for (; e + 8 <= e1; e += 8) {
                int s[8];
#pragma unroll
                for (int j = 0; j < 8; j++) s[j] = g_srcidx[e + j];
                float2 b[8];
#pragma unroll
                for (int j = 0; j < 8; j++) b[j] = __half22float2(Bh2[s[j] * 32 + lane]);
#pragma unroll
                for (int j = 0; j < 8; j++) {
                    acc0 += fmaxf(a.x + b[j].x, 0.f);
                    acc1 += fmaxf(a.y + b[j].y, 0.f);
                }
            }
            if (e + 4 <= e1) {
                int s[4];
#pragma unroll
                for (int j = 0; j < 4; j++) s[j] = g_srcidx[e + j];
                float2 b[4];
#pragma unroll
                for (int j = 0; j < 4; j++) b[j] = __half22float2(Bh2[s[j] * 32 + lane]);
#pragma unroll
                for (int j = 0; j < 4; j++) {
                    acc0 += fmaxf(a.x + b[j].x, 0.f);
                    acc1 += fmaxf(a.y + b[j].y, 0.f);
                }
                e += 4;
            }
            for (; e < e1; e++) {
                int s = g_srcidx[e];
                float2 bb = __half22float2(Bh2[s * 32 + lane]);
                acc0 += fmaxf(a.x + bb.x, 0.f);
                acc1 += fmaxf(a.y + bb.y, 0.f);
            }
            if (deg > 0) {
                float inv = 1.0f / (float)deg;
                acc0 *= inv;
                acc1 *= inv;
            }
        }
        dg[ni] = deg;
        accsh[warp][2 * lane][ni] = acc0;
        accsh[warp][2 * lane + 1][ni] = acc1;
    }
    __syncwarp();

    // fused 4-node epilogue GEMM in packed f32x2
    ull accA[4];
    {
        ull binit = pack2(bshm[2 * lane], bshm[2 * lane + 1]);
#pragma unroll
        for (int ni = 0; ni < 4; ni++) accA[ni] = binit;
    }
#pragma unroll 8
    for (int k = 0; k < 64; k++) {
        float4 av = *(const float4*)&accsh[warp][k][0];
        ull w2 = *(const ull*)&wsh[k * 64 + 2 * lane];
        fma2(accA[0], pack2(av.x, av.x), w2);
        fma2(accA[1], pack2(av.y, av.y), w2);
        fma2(accA[2], pack2(av.z, av.z), w2);
        fma2(accA[3], pack2(av.w, av.w), w2);
    }

    if (FINAL == 0) {
#pragma unroll
        for (int ni = 0; ni < 4; ni++) {
            int node = nbase + ni;
            if (node >= N_NODES) break;
            float o0, o1;
            unpack2(accA[ni], o0, o1);
            if (dg[ni] > 0) { o0 = fmaxf(o0, 0.f); o1 = fmaxf(o1, 0.f); }
            else            { o0 = 0.f; o1 = 0.f; }
            ((__half2*)g_Hh)[node * 32 + lane] = __floats2half2_rn(o0, o1);
        }
    } else {
        float4 w = *(const float4*)&wl[lane * 4];
        float bl0 = bl[0], bl1 = bl[1];
#pragma unroll
        for (int ni = 0; ni < 4; ni++) {
            int node = nbase + ni;
            if (node >= N_NODES) break;
            float o0, o1;
            unpack2(accA[ni], o0, o1);
            if (dg[ni] > 0) { o0 = fmaxf(o0, 0.f); o1 = fmaxf(o1, 0.f); }
            else            { o0 = 0.f; o1 = 0.f; }
            float p0 = o0 * w.x + o1 * w.z;
            float p1 = o0 * w.y + o1 * w.w;
#pragma unroll
            for (int ofs = 16; ofs > 0; ofs >>= 1) {
                p0 += __shfl_xor_sync(0xffffffffu, p0, ofs);
                p1 += __shfl_xor_sync(0xffffffffu, p1, ofs);
            }
            if (lane == 0) {
                out[node * 2 + 0] = p0 + bl0;
                out[node * 2 + 1] = p1 + bl1;
            }
        }
    }
}

// ---------------- layer-2 node pre-GEMMs from H(fp16): 8 nodes/warp, f32x2 ---
__global__ void __launch_bounds__(256, 4) k_nodeAB2(const float* __restrict__ w2a,
                                                    const float* __restrict__ b2a) {
    __shared__ float wdb[64 * 32 * 4];
    __shared__ float bshm[64];
    __shared__ float hsh[8][64 * 8];
    int tid = threadIdx.x;
    for (int idx = tid; idx < 64 * 64; idx += 256) {
        int k = idx >> 6, col = idx & 63;
        float top = w2a[idx];
        float bot = w2a[64 * 64 + idx];
        int ln = col >> 1, comp = col & 1;
        wdb[(k * 32 + ln) * 4 + comp]     = top - bot;
        wdb[(k * 32 + ln) * 4 + 2 + comp] = bot;
    }
    if (tid < 64) bshm[tid] = b2a[tid];
    __syncthreads();
    int warp = tid >> 5, lane = tid & 31;
    int nbase = (blockIdx.x * 8 + warp) * 8;
    const __half2* __restrict__ Hh2 = (const __half2*)g_Hh;

#pragma unroll
    for (int ni = 0; ni < 8; ni++) {
        int node = nbase + ni;
        float2 h = (node < N_NODES) ? __half22float2(Hh2[node * 32 + lane])
                                    : make_float2(0.f, 0.f);
        hsh[warp][(2 * lane) * 8 + ni]     = h.x;
        hsh[warp][(2 * lane + 1) * 8 + ni] = h.y;
    }
    __syncwarp();

    ull A[8], C[8];
    ull binit = pack2(bshm[2 * lane], bshm[2 * lane + 1]);
#pragma unroll
    for (int ni = 0; ni < 8; ni++) { A[ni] = binit; C[ni] = 0ULL; }

#pragma unroll 4
    for (int k = 0; k < 64; k++) {
        float4 h03 = *(const float4*)&hsh[warp][k * 8];
        float4 h47 = *(const float4*)&hsh[warp][k * 8 + 4];
        const ull* wp = (const ull*)&wdb[(k * 32 + lane) * 4];
        ull wd2 = wp[0], wb2 = wp[1];
        ull hh;
        hh = pack2(h03.x, h03.x); fma2(A[0], hh, wd2); fma2(C[0], hh, wb2);
        hh = pack2(h03.y, h03.y); fma2(A[1], hh, wd2); fma2(C[1], hh, wb2);
        hh = pack2(h03.z, h03.z); fma2(A[2], hh, wd2); fma2(C[2], hh, wb2);
        hh = pack2(h03.w, h03.w); fma2(A[3], hh, wd2); fma2(C[3], hh, wb2);
        hh = pack2(h47.x, h47.x); fma2(A[4], hh, wd2); fma2(C[4], hh, wb2);
        hh = pack2(h47.y, h47.y); fma2(A[5], hh, wd2); fma2(C[5], hh, wb2);
        hh = pack2(h47.z, h47.z); fma2(A[6], hh, wd2); fma2(C[6], hh, wb2);
        hh = pack2(h47.w, h47.w); fma2(A[7], hh, wd2); fma2(C[7], hh, wb2);
    }
#pragma unroll
    for (int ni = 0; ni < 8; ni++) {
        int node = nbase + ni;
        if (node >= N_NODES) break;
        float ax, ay, cx, cy;
        unpack2(A[ni], ax, ay);
        unpack2(C[ni], cx, cy);
        *(float2*)&g_A[node * 64 + lane * 2] = make_float2(ax, ay);
        ((__half2*)g_Bh)[node * 32 + lane] = __floats2half2_rn(cx, cy);
    }
}

extern "C" void kernel_launch(void* const* d_in, const int* in_sizes, int n_in,
                              void* d_out, int out_size) {
    const float* x   = (const float*)d_in[0];
    const int*   ei  = (const int*)d_in[1];   // int32 (JAX default x64 disabled)
    const float* w1a = (const float*)d_in[2];
    const float* b1a = (const float*)d_in[3];
    const float* w1b = (const float*)d_in[4];
    const float* b1b = (const float*)d_in[5];
    const float* w2a = (const float*)d_in[6];
    const float* b2a = (const float*)d_in[7];
    const float* w2b = (const float*)d_in[8];
    const float* b2b = (const float*)d_in[9];
    const float* wl  = (const float*)d_in[10];
    const float* bl  = (const float*)d_in[11];
    float* out = (float*)d_out;

    // CSR build: count(+packed rank) -> scan1 -> scan23(+re-zero deg) -> fill
    k_count<<<EPAIR_BLOCKS, 256>>>(ei);
    k_scan1<<<SCAN_BLOCKS, 256>>>();
    k_scan23<<<SCAN_BLOCKS, 256>>>();
    k_fill<<<EPAIR_BLOCKS, 256>>>(ei);

    int gather_blocks = (N_NODES + 31) / 32;   // 8 warps x 4 nodes
    int ab2_blocks    = (N_NODES + 63) / 64;   // 8 warps x 8 nodes

    // layer 1
    k_nodeAB1<<<gather_blocks, 256>>>(x, w1a, b1a);
    k_gather_t<0><<<gather_blocks, 256>>>(w1b, b1b, wl, bl, out);

    // layer 2 (+ fused final projection)
    k_nodeAB2<<<ab2_blocks, 256>>>(w2a, b2a);
    k_gather_t<1><<<gather_blocks, 256>>>(w2b, b2b, wl, bl, out);
}

// round 11
// speedup vs baseline: 1.0921x; 1.0484x over previous
#include <cuda_runtime.h>
#include <cuda_fp16.h>

#define N_NODES 50000
#define N_EDGES 800000
#define HID 64
#define SCAN_BLOCKS ((N_NODES + 255) / 256)       // 196
#define EPAIR_BLOCKS ((N_EDGES / 2 + 255) / 256)  // 1563

// ---- scratch (static device globals; zero-initialized at load) ----
__device__ int    g_deg[N_NODES];       // re-zeroed by k_scan23 each call
__device__ int    g_off[N_NODES + 1];
__device__ int    g_rank[N_EDGES];      // packed: (rank << 16) | dst
__device__ int    g_bsum[256];
__device__ int    g_srcidx[N_EDGES];
__device__ float  g_A[N_NODES * HID];
__device__ __half g_Bh[N_NODES * HID];  // B table in fp16
__device__ __half g_Hh[N_NODES * HID];  // H in fp16 (layer-1 output)

typedef unsigned long long ull;

// ---- packed f32x2 helpers (identical .rn rounding to scalar fp32) ----
__device__ __forceinline__ ull pack2(float x, float y) {
    ull r;
    asm("mov.b64 %0, {%1, %2};" : "=l"(r) : "f"(x), "f"(y));
    return r;
}
__device__ __forceinline__ void unpack2(ull v, float& x, float& y) {
    asm("mov.b64 {%0, %1}, %2;" : "=f"(x), "=f"(y) : "l"(v));
}
__device__ __forceinline__ void fma2(ull& acc, ull a, ull b) {
    asm("fma.rn.f32x2 %0, %1, %2, %0;" : "+l"(acc) : "l"(a), "l"(b));
}

// ---------------- CSR build ----------------
// vectorized single atomic pass: degree histogram + packed (rank|dst) per edge
__global__ void k_count(const int* __restrict__ ei) {
    int t = blockIdx.x * blockDim.x + threadIdx.x;
    int e = 2 * t;
    if (e + 1 < N_EDGES) {
        int2 d = *(const int2*)&ei[N_EDGES + e];
        int r0 = atomicAdd(&g_deg[d.x], 1);
        int r1 = atomicAdd(&g_deg[d.y], 1);
        *(int2*)&g_rank[e] = make_int2((r0 << 16) | d.x, (r1 << 16) | d.y);
    } else if (e < N_EDGES) {
        int dst = ei[N_EDGES + e];
        int r = atomicAdd(&g_deg[dst], 1);
        g_rank[e] = (r << 16) | dst;
    }
}

__global__ void k_scan1() {
    __shared__ int sh[256];
    int tid = threadIdx.x;
    int i = blockIdx.x * 256 + tid;
    int v = (i < N_NODES) ? g_deg[i] : 0;
    sh[tid] = v;
    __syncthreads();
#pragma unroll
    for (int ofs = 1; ofs < 256; ofs <<= 1) {
        int t = (tid >= ofs) ? sh[tid - ofs] : 0;
        __syncthreads();
        sh[tid] += t;
        __syncthreads();
    }
    if (i < N_NODES) g_off[i] = sh[tid] - v;
    if (tid == 255) g_bsum[blockIdx.x] = sh[255];
}

// merged scan2+scan3 + re-zero g_deg for next invocation
__global__ void k_scan23() {
    __shared__ int sh[256];
    int tid = threadIdx.x;
    int v = (tid < SCAN_BLOCKS) ? g_bsum[tid] : 0;
    sh[tid] = v;
    __syncthreads();
#pragma unroll
    for (int ofs = 1; ofs < 256; ofs <<= 1) {
        int t = (tid >= ofs) ? sh[tid - ofs] : 0;
        __syncthreads();
        sh[tid] += t;
        __syncthreads();
    }
    int prefix = (blockIdx.x == 0) ? 0 : sh[blockIdx.x - 1];
    int i = blockIdx.x * 256 + tid;
    if (i < N_NODES) {
        g_off[i] += prefix;
        g_deg[i] = 0;
    }
    if (blockIdx.x == 0 && tid == 0) g_off[N_NODES] = sh[255];
}

// atomic-free fill from packed rank|dst: position = off[dst] + rank
__global__ void k_fill(const int* __restrict__ ei) {
    int t = blockIdx.x * blockDim.x + threadIdx.x;
    int e = 2 * t;
    if (e + 1 < N_EDGES) {
        int2 r = *(const int2*)&g_rank[e];
        int2 s = *(const int2*)&ei[e];
        g_srcidx[g_off[r.x & 0xFFFF] + (r.x >> 16)] = s.x;
        g_srcidx[g_off[r.y & 0xFFFF] + (r.y >> 16)] = s.y;
    } else if (e < N_EDGES) {
        int r = g_rank[e];
        g_srcidx[g_off[r & 0xFFFF] + (r >> 16)] = ei[e];
    }
}

// ---------------- layer-1 node pre-GEMMs: A = x@(Wtop-Wbot)+b, B = x@Wbot ----
__global__ void __launch_bounds__(256, 3) k_nodeAB1(const float* __restrict__ x,
                                                    const float* __restrict__ w1a,
                                                    const float* __restrict__ b1a) {
    __shared__ float wd[16 * 64];
    __shared__ float wb[16 * 64];
    __shared__ float bshm[64];
    int tid = threadIdx.x;
    for (int i = tid; i < 16 * 64; i += 256) {
        float top = w1a[i];
        float bot = w1a[16 * 64 + i];
        wd[i] = top - bot;
        wb[i] = bot;
    }
    if (tid < 64) bshm[tid] = b1a[tid];
    __syncthreads();
    int warp = tid >> 5, lane = tid & 31;
    int nbase = (blockIdx.x * 8 + warp) * 4;
#pragma unroll
    for (int ni = 0; ni < 4; ni++) {
        int node = nbase + ni;
        if (node >= N_NODES) break;
        float xown = (lane < 16) ? x[node * 16 + lane] : 0.f;
        ull A = pack2(bshm[2 * lane], bshm[2 * lane + 1]);
        ull C = 0ULL;
#pragma unroll
        for (int k = 0; k < 16; k++) {
            float xk = __shfl_sync(0xffffffffu, xown, k);
            ull x2 = pack2(xk, xk);
            fma2(A, x2, *(const ull*)&wd[k * 64 + lane * 2]);
            fma2(C, x2, *(const ull*)&wb[k * 64 + lane * 2]);
        }
        float ax, ay, cx, cy;
        unpack2(A, ax, ay);
        unpack2(C, cx, cy);
        *(float2*)&g_A[node * 64 + lane * 2] = make_float2(ax, ay);
        ((__half2*)g_Bh)[node * 32 + lane] = __floats2half2_rn(cx, cy);
    }
}

// ---------------- edge gather + post-GEMM (both layers; FINAL fuses projection)
// per node i: acc = mean_e relu(A[i] + B[src_e]); h = relu(acc@Wp + bp)
template <int FINAL>
__global__ void __launch_bounds__(256, 3) k_gather_t(const float* __restrict__ Wp,
                                                     const float* __restrict__ bp,
                                                     const float* __restrict__ wl,
                                                     const float* __restrict__ bl,
                                                     float* __restrict__ out) {
    __shared__ float wsh[64 * 64];
    __shared__ float bshm[64];
    __shared__ float accsh[8][64][4];   // [warp][channel][node-in-warp]
    int tid = threadIdx.x;
    for (int i = tid; i < 64 * 64; i += 256) wsh[i] = Wp[i];
    if (tid < 64) bshm[tid] = bp[tid];
    __syncthreads();
    int warp = tid >> 5, lane = tid & 31;
    int nbase = (blockIdx.x * 8 + warp) * 4;
    const __half2* __restrict__ Bh2 = (const __half2*)g_Bh;

    int dg[4];
#pragma unroll
    for (int ni = 0; ni < 4; ni++) {
        int node = nbase + ni;
        float acc0 = 0.f, acc1 = 0.f;
        int deg = 0;
        if (node < N_NODES) {
            int e0 = g_off[node], e1 = g_off[node + 1];
            deg = e1 - e0;
            float2 a = *(const float2*)&g_A[node * 64 + lane * 2];
            int e = e0;
            for (; e + 8 <= e1; e += 8) {
                int s[8];
#pragma unroll
                for (int j = 0; j < 8; j++) s[j] = g_srcidx[e + j];
                float2 b[8];
#pragma unroll
                for (int j = 0; j < 8; j++) b[j] = __half22float2(Bh2[s[j] * 32 + lane]);
#pragma unroll
                for (int j = 0; j < 8; j++) {
                    acc0 += fmaxf(a.x + b[j].x, 0.f);
                    acc1 += fmaxf(a.y + b[j].y, 0.f);
                }
            }
            if (e + 4 <= e1) {
                int s[4];
#pragma unroll
                for (int j = 0; j < 4; j++) s[j] = g_srcidx[e + j];
                float2 b[4];
#pragma unroll
                for (int j = 0; j < 4; j++) b[j] = __half22float2(Bh2[s[j] * 32 + lane]);
#pragma unroll
                for (int j = 0; j < 4; j++) {
                    acc0 += fmaxf(a.x + b[j].x, 0.f);
                    acc1 += fmaxf(a.y + b[j].y, 0.f);
                }
                e += 4;
            }
            for (; e < e1; e++) {
                int s = g_srcidx[e];
                float2 bb = __half22float2(Bh2[s * 32 + lane]);
                acc0 += fmaxf(a.x + bb.x, 0.f);
                acc1 += fmaxf(a.y + bb.y, 0.f);
            }
            if (deg > 0) {
                float inv = 1.0f / (float)deg;
                acc0 *= inv;
                acc1 *= inv;
            }
        }
        dg[ni] = deg;
        accsh[warp][2 * lane][ni] = acc0;
        accsh[warp][2 * lane + 1][ni] = acc1;
    }
    __syncwarp();

    // fused 4-node epilogue GEMM in packed f32x2
    ull accA[4];
    {
        ull binit = pack2(bshm[2 * lane], bshm[2 * lane + 1]);
#pragma unroll
        for (int ni = 0; ni < 4; ni++) accA[ni] = binit;
    }
#pragma unroll 8
    for (int k = 0; k < 64; k++) {
        float4 av = *(const float4*)&accsh[warp][k][0];
        ull w2 = *(const ull*)&wsh[k * 64 + 2 * lane];
        fma2(accA[0], pack2(av.x, av.x), w2);
        fma2(accA[1], pack2(av.y, av.y), w2);
        fma2(accA[2], pack2(av.z, av.z), w2);
        fma2(accA[3], pack2(av.w, av.w), w2);
    }

    if (FINAL == 0) {
#pragma unroll
        for (int ni = 0; ni < 4; ni++) {
            int node = nbase + ni;
            if (node >= N_NODES) break;
            float o0, o1;
            unpack2(accA[ni], o0, o1);
            if (dg[ni] > 0) { o0 = fmaxf(o0, 0.f); o1 = fmaxf(o1, 0.f); }
            else            { o0 = 0.f; o1 = 0.f; }
            ((__half2*)g_Hh)[node * 32 + lane] = __floats2half2_rn(o0, o1);
        }
    } else {
        float4 w = *(const float4*)&wl[lane * 4];
        float bl0 = bl[0], bl1 = bl[1];
#pragma unroll
        for (int ni = 0; ni < 4; ni++) {
            int node = nbase + ni;
            if (node >= N_NODES) break;
            float o0, o1;
            unpack2(accA[ni], o0, o1);
            if (dg[ni] > 0) { o0 = fmaxf(o0, 0.f); o1 = fmaxf(o1, 0.f); }
            else            { o0 = 0.f; o1 = 0.f; }
            float p0 = o0 * w.x + o1 * w.z;
            float p1 = o0 * w.y + o1 * w.w;
#pragma unroll
            for (int ofs = 16; ofs > 0; ofs >>= 1) {
                p0 += __shfl_xor_sync(0xffffffffu, p0, ofs);
                p1 += __shfl_xor_sync(0xffffffffu, p1, ofs);
            }
            if (lane == 0) {
                out[node * 2 + 0] = p0 + bl0;
                out[node * 2 + 1] = p1 + bl1;
            }
        }
    }
}

// ---------------- layer-2 node pre-GEMMs from H(fp16): 8 nodes/warp, f32x2 ---
__global__ void __launch_bounds__(256, 3) k_nodeAB2(const float* __restrict__ w2a,
                                                    const float* __restrict__ b2a) {
    __shared__ float wdb[64 * 32 * 4];
    __shared__ float bshm[64];
    __shared__ float hsh[8][64 * 8];
    int tid = threadIdx.x;
    for (int idx = tid; idx < 64 * 64; idx += 256) {
        int k = idx >> 6, col = idx & 63;
        float top = w2a[idx];
        float bot = w2a[64 * 64 + idx];
        int ln = col >> 1, comp = col & 1;
        wdb[(k * 32 + ln) * 4 + comp]     = top - bot;
        wdb[(k * 32 + ln) * 4 + 2 + comp] = bot;
    }
    if (tid < 64) bshm[tid] = b2a[tid];
    __syncthreads();
    int warp = tid >> 5, lane = tid & 31;
    int nbase = (blockIdx.x * 8 + warp) * 8;
    const __half2* __restrict__ Hh2 = (const __half2*)g_Hh;

#pragma unroll
    for (int ni = 0; ni < 8; ni++) {
        int node = nbase + ni;
        float2 h = (node < N_NODES) ? __half22float2(Hh2[node * 32 + lane])
                                    : make_float2(0.f, 0.f);
        hsh[warp][(2 * lane) * 8 + ni]     = h.x;
        hsh[warp][(2 * lane + 1) * 8 + ni] = h.y;
    }
    __syncwarp();

    ull A[8], C[8];
    ull binit = pack2(bshm[2 * lane], bshm[2 * lane + 1]);
#pragma unroll
    for (int ni = 0; ni < 8; ni++) { A[ni] = binit; C[ni] = 0ULL; }

#pragma unroll 4
    for (int k = 0; k < 64; k++) {
        float4 h03 = *(const float4*)&hsh[warp][k * 8];
        float4 h47 = *(const float4*)&hsh[warp][k * 8 + 4];
        const ull* wp = (const ull*)&wdb[(k * 32 + lane) * 4];
        ull wd2 = wp[0], wb2 = wp[1];
        ull hh;
        hh = pack2(h03.x, h03.x); fma2(A[0], hh, wd2); fma2(C[0], hh, wb2);
        hh = pack2(h03.y, h03.y); fma2(A[1], hh, wd2); fma2(C[1], hh, wb2);
        hh = pack2(h03.z, h03.z); fma2(A[2], hh, wd2); fma2(C[2], hh, wb2);
        hh = pack2(h03.w, h03.w); fma2(A[3], hh, wd2); fma2(C[3], hh, wb2);
        hh = pack2(h47.x, h47.x); fma2(A[4], hh, wd2); fma2(C[4], hh, wb2);
        hh = pack2(h47.y, h47.y); fma2(A[5], hh, wd2); fma2(C[5], hh, wb2);
        hh = pack2(h47.z, h47.z); fma2(A[6], hh, wd2); fma2(C[6], hh, wb2);
        hh = pack2(h47.w, h47.w); fma2(A[7], hh, wd2); fma2(C[7], hh, wb2);
    }
#pragma unroll
    for (int ni = 0; ni < 8; ni++) {
        int node = nbase + ni;
        if (node >= N_NODES) break;
        float ax, ay, cx, cy;
        unpack2(A[ni], ax, ay);
        unpack2(C[ni], cx, cy);
        *(float2*)&g_A[node * 64 + lane * 2] = make_float2(ax, ay);
        ((__half2*)g_Bh)[node * 32 + lane] = __floats2half2_rn(cx, cy);
    }
}

extern "C" void kernel_launch(void* const* d_in, const int* in_sizes, int n_in,
                              void* d_out, int out_size) {
    const float* x   = (const float*)d_in[0];
    const int*   ei  = (const int*)d_in[1];   // int32 (JAX default x64 disabled)
    const float* w1a = (const float*)d_in[2];
    const float* b1a = (const float*)d_in[3];
    const float* w1b = (const float*)d_in[4];
    const float* b1b = (const float*)d_in[5];
    const float* w2a = (const float*)d_in[6];
    const float* b2a = (const float*)d_in[7];
    const float* w2b = (const float*)d_in[8];
    const float* b2b = (const float*)d_in[9];
    const float* wl  = (const float*)d_in[10];
    const float* bl  = (const float*)d_in[11];
    float* out = (float*)d_out;

    // CSR build: count(+packed rank) -> scan1 -> scan23(+re-zero deg) -> fill
    k_count<<<EPAIR_BLOCKS, 256>>>(ei);
    k_scan1<<<SCAN_BLOCKS, 256>>>();
    k_scan23<<<SCAN_BLOCKS, 256>>>();
    k_fill<<<EPAIR_BLOCKS, 256>>>(ei);

    int gather_blocks = (N_NODES + 31) / 32;   // 8 warps x 4 nodes
    int ab2_blocks    = (N_NODES + 63) / 64;   // 8 warps x 8 nodes

    // layer 1
    k_nodeAB1<<<gather_blocks, 256>>>(x, w1a, b1a);
    k_gather_t<0><<<gather_blocks, 256>>>(w1b, b1b, wl, bl, out);

    // layer 2 (+ fused final projection)
    k_nodeAB2<<<ab2_blocks, 256>>>(w2a, b2a);
    k_gather_t<1><<<gather_blocks, 256>>>(w2b, b2b, wl, bl, out);
}

// round 12
// speedup vs baseline: 1.2108x; 1.1087x over previous
#include <cuda_runtime.h>
#include <cuda_fp16.h>

#define N_NODES 50000
#define N_EDGES 800000
#define HID 64
#define SCAN_BLOCKS ((N_NODES + 255) / 256)       // 196
#define EPAIR_BLOCKS ((N_EDGES / 2 + 255) / 256)  // 1563
#define AB1_NPW 8
#define AB1_BLOCKS ((N_NODES + 8 * AB1_NPW - 1) / (8 * AB1_NPW))  // 782

// ---- scratch (static device globals; zero-initialized at load) ----
__device__ int    g_deg[N_NODES];       // re-zeroed by k_scan23 each call
__device__ int    g_off[N_NODES + 1];
__device__ int    g_rank[N_EDGES];      // packed: (rank << 16) | dst
__device__ int    g_bsum[256];
__device__ int    g_srcidx[N_EDGES];
__device__ float  g_A[N_NODES * HID];
__device__ __half g_Bh[N_NODES * HID];  // B table in fp16
__device__ __half g_Hh[N_NODES * HID];  // H in fp16 (layer-1 output)

typedef unsigned long long ull;

// ---- packed f32x2 helpers (identical .rn rounding to scalar fp32) ----
__device__ __forceinline__ ull pack2(float x, float y) {
    ull r;
    asm("mov.b64 %0, {%1, %2};" : "=l"(r) : "f"(x), "f"(y));
    return r;
}
__device__ __forceinline__ void unpack2(ull v, float& x, float& y) {
    asm("mov.b64 {%0, %1}, %2;" : "=f"(x), "=f"(y) : "l"(v));
}
__device__ __forceinline__ void fma2(ull& acc, ull a, ull b) {
    asm("fma.rn.f32x2 %0, %1, %2, %0;" : "+l"(acc) : "l"(a), "l"(b));
}

// ---------------- CSR build ----------------
// vectorized single atomic pass: degree histogram + packed (rank|dst) per edge
__global__ void k_count(const int* __restrict__ ei) {
    int t = blockIdx.x * blockDim.x + threadIdx.x;
    int e = 2 * t;
    if (e + 1 < N_EDGES) {
        int2 d = *(const int2*)&ei[N_EDGES + e];
        int r0 = atomicAdd(&g_deg[d.x], 1);
        int r1 = atomicAdd(&g_deg[d.y], 1);
        *(int2*)&g_rank[e] = make_int2((r0 << 16) | d.x, (r1 << 16) | d.y);
    } else if (e < N_EDGES) {
        int dst = ei[N_EDGES + e];
        int r = atomicAdd(&g_deg[dst], 1);
        g_rank[e] = (r << 16) | dst;
    }
}

__global__ void k_scan1() {
    __shared__ int sh[256];
    int tid = threadIdx.x;
    int i = blockIdx.x * 256 + tid;
    int v = (i < N_NODES) ? g_deg[i] : 0;
    sh[tid] = v;
    __syncthreads();
#pragma unroll
    for (int ofs = 1; ofs < 256; ofs <<= 1) {
        int t = (tid >= ofs) ? sh[tid - ofs] : 0;
        __syncthreads();
        sh[tid] += t;
        __syncthreads();
    }
    if (i < N_NODES) g_off[i] = sh[tid] - v;
    if (tid == 255) g_bsum[blockIdx.x] = sh[255];
}

// merged scan2+scan3 + re-zero g_deg for next invocation
__global__ void k_scan23() {
    __shared__ int sh[256];
    int tid = threadIdx.x;
    int v = (tid < SCAN_BLOCKS) ? g_bsum[tid] : 0;
    sh[tid] = v;
    __syncthreads();
#pragma unroll
    for (int ofs = 1; ofs < 256; ofs <<= 1) {
        int t = (tid >= ofs) ? sh[tid - ofs] : 0;
        __syncthreads();
        sh[tid] += t;
        __syncthreads();
    }
    int prefix = (blockIdx.x == 0) ? 0 : sh[blockIdx.x - 1];
    int i = blockIdx.x * 256 + tid;
    if (i < N_NODES) {
        g_off[i] += prefix;
        g_deg[i] = 0;
    }
    if (blockIdx.x == 0 && tid == 0) g_off[N_NODES] = sh[255];
}

// atomic-free fill from packed rank|dst: position = off[dst] + rank
__global__ void k_fill(const int* __restrict__ ei) {
    int t = blockIdx.x * blockDim.x + threadIdx.x;
    int e = 2 * t;
    if (e + 1 < N_EDGES) {
        int2 r = *(const int2*)&g_rank[e];
        int2 s = *(const int2*)&ei[e];
        g_srcidx[g_off[r.x & 0xFFFF] + (r.x >> 16)] = s.x;
        g_srcidx[g_off[r.y & 0xFFFF] + (r.y >> 16)] = s.y;
    } else if (e < N_EDGES) {
        int r = g_rank[e];
        g_srcidx[g_off[r & 0xFFFF] + (r >> 16)] = ei[e];
    }
}

// ---------------- layer-1 node pre-GEMMs: A = x@(Wtop-Wbot)+b, B = x@Wbot ----
// Weights live entirely in registers (16+16 packed ULLs per lane); zero LDS.
__global__ void __launch_bounds__(256) k_nodeAB1(const float* __restrict__ x,
                                                 const float* __restrict__ w1a,
                                                 const float* __restrict__ b1a) {
    int warp = threadIdx.x >> 5, lane = threadIdx.x & 31;
    ull wd[16], wb[16];
#pragma unroll
    for (int k = 0; k < 16; k++) {
        float2 top = *(const float2*)&w1a[k * 64 + 2 * lane];
        float2 bot = *(const float2*)&w1a[(16 + k) * 64 + 2 * lane];
        wd[k] = pack2(top.x - bot.x, top.y - bot.y);
        wb[k] = pack2(bot.x, bot.y);
    }
    float2 bias = *(const float2*)&b1a[2 * lane];
    ull binit = pack2(bias.x, bias.y);

    int nbase = (blockIdx.x * 8 + warp) * AB1_NPW;
    float xv[AB1_NPW];
#pragma unroll
    for (int ni = 0; ni < AB1_NPW; ni++) {
        int node = nbase + ni;
        xv[ni] = (node < N_NODES && lane < 16) ? x[node * 16 + lane] : 0.f;
    }
#pragma unroll
    for (int ni = 0; ni < AB1_NPW; ni++) {
        int node = nbase + ni;
        if (node >= N_NODES) break;
        ull A = binit, C = 0ULL;
#pragma unroll
        for (int k = 0; k < 16; k++) {
            float xk = __shfl_sync(0xffffffffu, xv[ni], k);
            ull x2 = pack2(xk, xk);
            fma2(A, x2, wd[k]);
            fma2(C, x2, wb[k]);
        }
        float ax, ay, cx, cy;
        unpack2(A, ax, ay);
        unpack2(C, cx, cy);
        *(float2*)&g_A[node * 64 + lane * 2] = make_float2(ax, ay);
        ((__half2*)g_Bh)[node * 32 + lane] = __floats2half2_rn(cx, cy);
    }
}

// ---------------- edge gather + post-GEMM (both layers; FINAL fuses projection)
// per node i: acc = mean_e relu(A[i] + B[src_e]); h = relu(acc@Wp + bp)
template <int FINAL>
__global__ void __launch_bounds__(256) k_gather_t(const float* __restrict__ Wp,
                                                  const float* __restrict__ bp,
                                                  const float* __restrict__ wl,
                                                  const float* __restrict__ bl,
                                                  float* __restrict__ out) {
    __shared__ float wsh[64 * 64];
    __shared__ float bshm[64];
    __shared__ float accsh[8][64][4];   // [warp][channel][node-in-warp]
    int tid = threadIdx.x;
    for (int i = tid; i < 64 * 64; i += 256) wsh[i] = Wp[i];
    if (tid < 64) bshm[tid] = bp[tid];
    __syncthreads();
    int warp = tid >> 5, lane = tid & 31;
    int nbase = (blockIdx.x * 8 + warp) * 4;
    const __half2* __restrict__ Bh2 = (const __half2*)g_Bh;

    int dg[4];
#pragma unroll
    for (int ni = 0; ni < 4; ni++) {
        int node = nbase + ni;
        float acc0 = 0.f, acc1 = 0.f;
        int deg = 0;
        if (node < N_NODES) {
            int e0 = g_off[node], e1 = g_off[node + 1];
            deg = e1 - e0;
            float2 a = *(const float2*)&g_A[node * 64 + lane * 2];
            int e = e0;
            for (; e + 8 <= e1; e += 8) {
                int s[8];
#pragma unroll
                for (int j = 0; j < 8; j++) s[j] = g_srcidx[e + j];
                float2 b[8];
#pragma unroll
                for (int j = 0; j < 8; j++) b[j] = __half22float2(Bh2[s[j] * 32 + lane]);
#pragma unroll
                for (int j = 0; j < 8; j++) {
                    acc0 += fmaxf(a.x + b[j].x, 0.f);
                    acc1 += fmaxf(a.y + b[j].y, 0.f);
                }
            }
            if (e + 4 <= e1) {
                int s[4];
#pragma unroll
                for (int j = 0; j < 4; j++) s[j] = g_srcidx[e + j];
                float2 b[4];
#pragma unroll
                for (int j = 0; j < 4; j++) b[j] = __half22float2(Bh2[s[j] * 32 + lane]);
#pragma unroll
                for (int j = 0; j < 4; j++) {
                    acc0 += fmaxf(a.x + b[j].x, 0.f);
                    acc1 += fmaxf(a.y + b[j].y, 0.f);
                }
                e += 4;
            }
            for (; e < e1; e++) {
                int s = g_srcidx[e];
                float2 bb = __half22float2(Bh2[s * 32 + lane]);
                acc0 += fmaxf(a.x + bb.x, 0.f);
                acc1 += fmaxf(a.y + bb.y, 0.f);
            }
            if (deg > 0) {
                float inv = 1.0f / (float)deg;
                acc0 *= inv;
                acc1 *= inv;
            }
        }
        dg[ni] = deg;
        accsh[warp][2 * lane][ni] = acc0;
        accsh[warp][2 * lane + 1][ni] = acc1;
    }
    __syncwarp();

    // fused 4-node epilogue GEMM in packed f32x2
    ull accA[4];
    {
        ull binit = pack2(bshm[2 * lane], bshm[2 * lane + 1]);
#pragma unroll
        for (int ni = 0; ni < 4; ni++) accA[ni] = binit;
    }
#pragma unroll 8
    for (int k = 0; k < 64; k++) {
        float4 av = *(const float4*)&accsh[warp][k][0];
        ull w2 = *(const ull*)&wsh[k * 64 + 2 * lane];
        fma2(accA[0], pack2(av.x, av.x), w2);
        fma2(accA[1], pack2(av.y, av.y), w2);
        fma2(accA[2], pack2(av.z, av.z), w2);
        fma2(accA[3], pack2(av.w, av.w), w2);
    }

    if (FINAL == 0) {
#pragma unroll
        for (int ni = 0; ni < 4; ni++) {
            int node = nbase + ni;
            if (node >= N_NODES) break;
            float o0, o1;
            unpack2(accA[ni], o0, o1);
            if (dg[ni] > 0) { o0 = fmaxf(o0, 0.f); o1 = fmaxf(o1, 0.f); }
            else            { o0 = 0.f; o1 = 0.f; }
            ((__half2*)g_Hh)[node * 32 + lane] = __floats2half2_rn(o0, o1);
        }
    } else {
        float4 w = *(const float4*)&wl[lane * 4];
        float bl0 = bl[0], bl1 = bl[1];
#pragma unroll
        for (int ni = 0; ni < 4; ni++) {
            int node = nbase + ni;
            if (node >= N_NODES) break;
            float o0, o1;
            unpack2(accA[ni], o0, o1);
            if (dg[ni] > 0) { o0 = fmaxf(o0, 0.f); o1 = fmaxf(o1, 0.f); }
            else            { o0 = 0.f; o1 = 0.f; }
            float p0 = o0 * w.x + o1 * w.z;
            float p1 = o0 * w.y + o1 * w.w;
#pragma unroll
            for (int ofs = 16; ofs > 0; ofs >>= 1) {
                p0 += __shfl_xor_sync(0xffffffffu, p0, ofs);
                p1 += __shfl_xor_sync(0xffffffffu, p1, ofs);
            }
            if (lane == 0) {
                out[node * 2 + 0] = p0 + bl0;
                out[node * 2 + 1] = p1 + bl1;
            }
        }
    }
}

// ---------------- layer-2 node pre-GEMMs from H(fp16): 8 nodes/warp, f32x2 ---
__global__ void __launch_bounds__(256) k_nodeAB2(const float* __restrict__ w2a,
                                                 const float* __restrict__ b2a) {
    __shared__ float wdb[64 * 32 * 4];
    __shared__ float bshm[64];
    __shared__ float hsh[8][64 * 8];
    int tid = threadIdx.x;
    for (int idx = tid; idx < 64 * 64; idx += 256) {
        int k = idx >> 6, col = idx & 63;
        float top = w2a[idx];
        float bot = w2a[64 * 64 + idx];
        int ln = col >> 1, comp = col & 1;
        wdb[(k * 32 + ln) * 4 + comp]     = top - bot;
        wdb[(k * 32 + ln) * 4 + 2 + comp] = bot;
    }
    if (tid < 64) bshm[tid] = b2a[tid];
    __syncthreads();
    int warp = tid >> 5, lane = tid & 31;
    int nbase = (blockIdx.x * 8 + warp) * 8;
    const __half2* __restrict__ Hh2 = (const __half2*)g_Hh;

#pragma unroll
    for (int ni = 0; ni < 8; ni++) {
        int node = nbase + ni;
        float2 h = (node < N_NODES) ? __half22float2(Hh2[node * 32 + lane])
                                    : make_float2(0.f, 0.f);
        hsh[warp][(2 * lane) * 8 + ni]     = h.x;
        hsh[warp][(2 * lane + 1) * 8 + ni] = h.y;
    }
    __syncwarp();

    ull A[8], C[8];
    ull binit = pack2(bshm[2 * lane], bshm[2 * lane + 1]);
#pragma unroll
    for (int ni = 0; ni < 8; ni++) { A[ni] = binit; C[ni] = 0ULL; }

#pragma unroll 4
    for (int k = 0; k < 64; k++) {
        float4 h03 = *(const float4*)&hsh[warp][k * 8];
        float4 h47 = *(const float4*)&hsh[warp][k * 8 + 4];
        const ull* wp = (const ull*)&wdb[(k * 32 + lane) * 4];
        ull wd2 = wp[0], wb2 = wp[1];
        ull hh;
        hh = pack2(h03.x, h03.x); fma2(A[0], hh, wd2); fma2(C[0], hh, wb2);
        hh = pack2(h03.y, h03.y); fma2(A[1], hh, wd2); fma2(C[1], hh, wb2);
        hh = pack2(h03.z, h03.z); fma2(A[2], hh, wd2); fma2(C[2], hh, wb2);
        hh = pack2(h03.w, h03.w); fma2(A[3], hh, wd2); fma2(C[3], hh, wb2);
        hh = pack2(h47.x, h47.x); fma2(A[4], hh, wd2); fma2(C[4], hh, wb2);
        hh = pack2(h47.y, h47.y); fma2(A[5], hh, wd2); fma2(C[5], hh, wb2);
        hh = pack2(h47.z, h47.z); fma2(A[6], hh, wd2); fma2(C[6], hh, wb2);
        hh = pack2(h47.w, h47.w); fma2(A[7], hh, wd2); fma2(C[7], hh, wb2);
    }
#pragma unroll
    for (int ni = 0; ni < 8; ni++) {
        int node = nbase + ni;
        if (node >= N_NODES) break;
        float ax, ay, cx, cy;
        unpack2(A[ni], ax, ay);
        unpack2(C[ni], cx, cy);
        *(float2*)&g_A[node * 64 + lane * 2] = make_float2(ax, ay);
        ((__half2*)g_Bh)[node * 32 + lane] = __floats2half2_rn(cx, cy);
    }
}

extern "C" void kernel_launch(void* const* d_in, const int* in_sizes, int n_in,
                              void* d_out, int out_size) {
    const float* x   = (const float*)d_in[0];
    const int*   ei  = (const int*)d_in[1];   // int32 (JAX default x64 disabled)
    const float* w1a = (const float*)d_in[2];
    const float* b1a = (const float*)d_in[3];
    const float* w1b = (const float*)d_in[4];
    const float* b1b = (const float*)d_in[5];
    const float* w2a = (const float*)d_in[6];
    const float* b2a = (const float*)d_in[7];
    const float* w2b = (const float*)d_in[8];
    const float* b2b = (const float*)d_in[9];
    const float* wl  = (const float*)d_in[10];
    const float* bl  = (const float*)d_in[11];
    float* out = (float*)d_out;

    // CSR build: count(+packed rank) -> scan1 -> scan23(+re-zero deg) -> fill
    k_count<<<EPAIR_BLOCKS, 256>>>(ei);
    k_scan1<<<SCAN_BLOCKS, 256>>>();
    k_scan23<<<SCAN_BLOCKS, 256>>>();
    k_fill<<<EPAIR_BLOCKS, 256>>>(ei);

    int gather_blocks = (N_NODES + 31) / 32;   // 8 warps x 4 nodes
    int ab2_blocks    = (N_NODES + 63) / 64;   // 8 warps x 8 nodes

    // layer 1
    k_nodeAB1<<<AB1_BLOCKS, 256>>>(x, w1a, b1a);
    k_gather_t<0><<<gather_blocks, 256>>>(w1b, b1b, wl, bl, out);

    // layer 2 (+ fused final projection)
    k_nodeAB2<<<ab2_blocks, 256>>>(w2a, b2a);
    k_gather_t<1><<<gather_blocks, 256>>>(w2b, b2b, wl, bl, out);
}